// round 5
// baseline (speedup 1.0000x reference)
#include <cuda_runtime.h>

#define MAX_N 100000
#define MAX_E 1600000

// ---------------- scratch (static __device__ arrays) ----------------------
__device__ float g_h1  [MAX_N * 64];
__device__ float g_als1[MAX_N * 4];
__device__ float g_ald1[MAX_N * 4];
__device__ float g_out1[MAX_N * 64];
__device__ float g_als2[MAX_N * 4];
__device__ float g_ald2[MAX_N * 4];
__device__ float g_Z   [MAX_N * 256];
__device__ int   g_rowptr[MAX_N + 1];
__device__ int   g_cursor[MAX_N];
__device__ int   g_bsum[128];
__device__ int   g_ssrc[MAX_E];
__device__ float g_wsd [64 * 8];     // [k][q]: q<4 -> ws (a_src), q>=4 -> wd (a_dst)
__device__ float g_wcat[256 * 32];   // [h*64+k][c] = 0.25*W2[k][h*32+c]

// ---------------- GEMM: C[M,NC] = A[M,K] @ W[K,NC] ------------------------
template<int K, int NC>
__global__ __launch_bounds__(16 * (NC / 8))
void gemm_kernel(const float* __restrict__ A, const float* __restrict__ W,
                 float* __restrict__ C, int M)
{
    constexpr int KC = 32;
    constexpr int TX = NC / 8;
    constexpr int T  = 16 * TX;
    constexpr int A_F4 = (128 * KC / 4) / T;
    constexpr int B_F4 = (KC * NC / 4) / T;

    __shared__ float As[128][33];
    __shared__ float Bs[KC][NC];

    const int tid = threadIdx.x;
    const int tx = tid % TX;
    const int ty = tid / TX;
    const int row0 = blockIdx.x * 128;

    float4 aPre[A_F4], bPre[B_F4];

    auto loadA = [&](int kk) {
#pragma unroll
        for (int t = 0; t < A_F4; t++) {
            int q = tid + t * T;
            int r = q >> 3, kc4 = q & 7;
            int gr = row0 + r;
            aPre[t] = (gr < M)
                ? *(const float4*)(A + (size_t)gr * K + kk + kc4 * 4)
                : make_float4(0.f, 0.f, 0.f, 0.f);
        }
    };
    auto loadB = [&](int kk) {
#pragma unroll
        for (int t = 0; t < B_F4; t++) {
            int q = tid + t * T;
            int r = q / (NC / 4), c4 = q % (NC / 4);
            bPre[t] = *(const float4*)(W + (size_t)(kk + r) * NC + c4 * 4);
        }
    };
    auto storeA = [&]() {
#pragma unroll
        for (int t = 0; t < A_F4; t++) {
            int q = tid + t * T;
            int r = q >> 3, kc4 = q & 7;
            As[r][kc4 * 4 + 0] = aPre[t].x;
            As[r][kc4 * 4 + 1] = aPre[t].y;
            As[r][kc4 * 4 + 2] = aPre[t].z;
            As[r][kc4 * 4 + 3] = aPre[t].w;
        }
    };
    auto storeB = [&]() {
#pragma unroll
        for (int t = 0; t < B_F4; t++) {
            int q = tid + t * T;
            int r = q / (NC / 4), c4 = q % (NC / 4);
            *(float4*)&Bs[r][c4 * 4] = bPre[t];
        }
    };

    float acc[8][8];
#pragma unroll
    for (int i = 0; i < 8; i++)
#pragma unroll
        for (int j = 0; j < 8; j++) acc[i][j] = 0.f;

    loadA(0); loadB(0);
    storeA(); storeB();
    __syncthreads();

    for (int kk = KC; kk <= K; kk += KC) {
        const bool more = (kk < K);
        if (more) { loadA(kk); loadB(kk); }

#pragma unroll
        for (int k = 0; k < KC; k++) {
            float a[8];
#pragma unroll
            for (int i = 0; i < 8; i++) a[i] = As[ty * 8 + i][k];
            float4 b0 = *(float4*)&Bs[k][tx * 8];
            float4 b1 = *(float4*)&Bs[k][tx * 8 + 4];
#pragma unroll
            for (int i = 0; i < 8; i++) {
                acc[i][0] = fmaf(a[i], b0.x, acc[i][0]);
                acc[i][1] = fmaf(a[i], b0.y, acc[i][1]);
                acc[i][2] = fmaf(a[i], b0.z, acc[i][2]);
                acc[i][3] = fmaf(a[i], b0.w, acc[i][3]);
                acc[i][4] = fmaf(a[i], b1.x, acc[i][4]);
                acc[i][5] = fmaf(a[i], b1.y, acc[i][5]);
                acc[i][6] = fmaf(a[i], b1.z, acc[i][6]);
                acc[i][7] = fmaf(a[i], b1.w, acc[i][7]);
            }
        }
        __syncthreads();
        if (more) {
            storeA(); storeB();
            __syncthreads();
        }
    }

#pragma unroll
    for (int i = 0; i < 8; i++) {
        int gr = row0 + ty * 8 + i;
        if (gr < M) {
            *(float4*)(C + (size_t)gr * NC + tx * 8) =
                make_float4(acc[i][0], acc[i][1], acc[i][2], acc[i][3]);
            *(float4*)(C + (size_t)gr * NC + tx * 8 + 4) =
                make_float4(acc[i][4], acc[i][5], acc[i][6], acc[i][7]);
        }
    }
}

// ---------------- attention logits (layer 1) -------------------------------
template<int C>
__global__ void al_kernel(const float* __restrict__ h,
                          const float* __restrict__ a_src,
                          const float* __restrict__ a_dst,
                          float* __restrict__ als, float* __restrict__ ald, int n)
{
    int t = blockIdx.x * blockDim.x + threadIdx.x;
    if (t >= n * 4) return;
    int node = t >> 2, head = t & 3;
    const float* hp  = h + (size_t)node * (4 * C) + head * C;
    const float* asp = a_src + head * C;
    const float* adp = a_dst + head * C;
    float s1 = 0.f, s2 = 0.f;
#pragma unroll
    for (int c = 0; c < C; c += 4) {
        float4 hv = *(const float4*)(hp + c);
        float4 av = *(const float4*)(asp + c);
        float4 dv = *(const float4*)(adp + c);
        s1 += hv.x * av.x + hv.y * av.y + hv.z * av.z + hv.w * av.w;
        s2 += hv.x * dv.x + hv.y * dv.y + hv.z * dv.z + hv.w * dv.w;
    }
    als[t] = s1;
    ald[t] = s2;
}

// ---------------- CSR build ------------------------------------------------
__global__ void hist_kernel(const int* __restrict__ de, int E, int* __restrict__ cnt)
{
    int e = blockIdx.x * blockDim.x + threadIdx.x;
    if (e < E) atomicAdd(&cnt[de[e]], 1);
}

__global__ void scan_k1(int* __restrict__ data, int n, int* __restrict__ bsum)
{
    __shared__ int sh[256];
    int base = blockIdx.x * 2048 + threadIdx.x * 8;
    int v[8];
    int run = 0;
#pragma unroll
    for (int k = 0; k < 8; k++) {
        int t = (base + k < n) ? data[base + k] : 0;
        v[k] = run;
        run += t;
    }
    sh[threadIdx.x] = run;
    __syncthreads();
    for (int off = 1; off < 256; off <<= 1) {
        int t = (threadIdx.x >= off) ? sh[threadIdx.x - off] : 0;
        __syncthreads();
        sh[threadIdx.x] += t;
        __syncthreads();
    }
    int excl = sh[threadIdx.x] - run;
#pragma unroll
    for (int k = 0; k < 8; k++)
        if (base + k < n) data[base + k] = v[k] + excl;
    if (threadIdx.x == 255) bsum[blockIdx.x] = sh[255];
}

__global__ void scan_k2(int* __restrict__ bsum, int nb)
{
    if (threadIdx.x == 0) {
        int run = 0;
        for (int i = 0; i < nb; i++) { int t = bsum[i]; bsum[i] = run; run += t; }
    }
}

__global__ void scan_k3(int* __restrict__ data, int n, const int* __restrict__ bsum,
                        int* __restrict__ cursor, int E)
{
    int i = blockIdx.x * blockDim.x + threadIdx.x;
    if (i < n) {
        int v = data[i] + bsum[i >> 11];
        data[i] = v;
        cursor[i] = v;
    }
    if (i == 0) data[n] = E;
}

__global__ void scatter_kernel(const int* __restrict__ se, const int* __restrict__ de,
                               int E, int* __restrict__ cursor, int* __restrict__ ssrc)
{
    int e = blockIdx.x * blockDim.x + threadIdx.x;
    if (e < E) {
        int pos = atomicAdd(&cursor[de[e]], 1);
        ssrc[pos] = se[e];
    }
}

// ---------------- weight folds for layer 2 ---------------------------------
// wsd[k][q] = sum_c W2[k, h*32+c] * a{src|dst}2[h, c],  h = q&3
__global__ void build_wsd(const float* __restrict__ W2,
                          const float* __restrict__ as2,
                          const float* __restrict__ ad2,
                          float* __restrict__ wsd)
{
    int t = threadIdx.x;
    if (t >= 512) return;
    int k = t >> 3, q = t & 7, h = q & 3;
    const float* a = (q < 4) ? as2 : ad2;
    float s = 0.f;
#pragma unroll
    for (int c = 0; c < 32; c++)
        s += W2[(size_t)k * 128 + h * 32 + c] * a[h * 32 + c];
    wsd[k * 8 + q] = s;
}

// wcat[h*64+k][c] = 0.25 * W2[k][h*32+c]
__global__ void build_wcat(const float* __restrict__ W2, float* __restrict__ wcat)
{
    int t = blockIdx.x * blockDim.x + threadIdx.x;
    if (t >= 8192) return;
    int kk = t >> 5, c = t & 31;
    int h = kk >> 6, k = kk & 63;
    wcat[t] = 0.25f * W2[(size_t)k * 128 + h * 32 + c];
}

// ---------------- layer-2 logits from out1 (warp per node) ----------------
__global__ void als2_kernel(const float* __restrict__ out1,
                            const float* __restrict__ wsd,
                            float* __restrict__ als, float* __restrict__ ald, int n)
{
    __shared__ float sw[512];
    for (int i = threadIdx.x; i < 512; i += blockDim.x) sw[i] = wsd[i];
    __syncthreads();

    int lane = threadIdx.x & 31;
    int node = (blockIdx.x * blockDim.x + threadIdx.x) >> 5;
    if (node >= n) return;

    float2 z = *(const float2*)(out1 + (size_t)node * 64 + lane * 2);
    float acc[8];
#pragma unroll
    for (int q = 0; q < 8; q++)
        acc[q] = z.x * sw[(lane * 2) * 8 + q] + z.y * sw[(lane * 2 + 1) * 8 + q];
#pragma unroll
    for (int off = 16; off > 0; off >>= 1)
#pragma unroll
        for (int q = 0; q < 8; q++)
            acc[q] += __shfl_xor_sync(0xffffffffu, acc[q], off);
    if (lane == 0) {
        *(float4*)(als + (size_t)node * 4) = make_float4(acc[0], acc[1], acc[2], acc[3]);
        *(float4*)(ald + (size_t)node * 4) = make_float4(acc[4], acc[5], acc[6], acc[7]);
    }
}

// ---------------- fused softmax-aggregate, CSR (layer 1) -------------------
template<int C>
__global__ void agg_csr_kernel(const int* __restrict__ rowptr,
                               const int* __restrict__ ssrc,
                               const float* __restrict__ als,
                               const float* __restrict__ ald,
                               const float* __restrict__ h,
                               const float* __restrict__ bias,
                               float* __restrict__ out, int n)
{
    constexpr int HC = 4 * C;
    constexpr int G  = HC / 4;
    int gt   = blockIdx.x * blockDim.x + threadIdx.x;
    int node = gt / G;
    int li   = gt % G;
    if (node >= n) return;
    int head = li / (C / 4);

    float aldv = ald[(size_t)node * 4 + head];

    float e0 = als[(size_t)node * 4 + head] + aldv;
    e0 = e0 > 0.f ? e0 : 0.2f * e0;
    float ex = __expf(e0);
    float den = ex;
    float4 hv = ((const float4*)(h + (size_t)node * HC))[li];
    float4 acc = make_float4(ex * hv.x, ex * hv.y, ex * hv.z, ex * hv.w);

    int j1 = rowptr[node + 1];
    for (int j = rowptr[node]; j < j1; j++) {
        int s = ssrc[j];
        float e = als[(size_t)s * 4 + head] + aldv;
        e = e > 0.f ? e : 0.2f * e;
        float w = __expf(e);
        den += w;
        float4 v = ((const float4*)(h + (size_t)s * HC))[li];
        acc.x = fmaf(w, v.x, acc.x);
        acc.y = fmaf(w, v.y, acc.y);
        acc.z = fmaf(w, v.z, acc.z);
        acc.w = fmaf(w, v.w, acc.w);
    }
    float inv = 1.f / den;
    float4 o;
    o.x = acc.x * inv + bias[li * 4 + 0];
    o.y = acc.y * inv + bias[li * 4 + 1];
    o.z = acc.z * inv + bias[li * 4 + 2];
    o.w = acc.w * inv + bias[li * 4 + 3];
    ((float4*)(out + (size_t)node * HC))[li] = o;
}

// ---------------- layer-2 aggregation in INPUT space (warp per node) ------
// Z[node, h*64+k] = (sum_{s in N(node)+self} w_sh * out1[s,k]) / den_h
__global__ void agg2_dual_kernel(const int* __restrict__ rowptr,
                                 const int* __restrict__ ssrc,
                                 const float* __restrict__ als,
                                 const float* __restrict__ ald,
                                 const float* __restrict__ out1,
                                 float* __restrict__ Z, int n)
{
    int lane = threadIdx.x & 31;
    int node = (blockIdx.x * blockDim.x + threadIdx.x) >> 5;
    if (node >= n) return;
    int hq = lane & 3;

    float4 ad = *(const float4*)(ald + (size_t)node * 4);
    float adq = (hq == 0) ? ad.x : (hq == 1) ? ad.y : (hq == 2) ? ad.z : ad.w;

    float2 acc0 = make_float2(0.f, 0.f), acc1 = acc0, acc2 = acc0, acc3 = acc0;
    float denl = 0.f;

    int j0 = rowptr[node], j1 = rowptr[node + 1];
    int s = node;                       // self-loop first
    for (int j = j0 - 1; j < j1; j++) {
        if (j >= j0) s = ssrc[j];
        float4 s4 = *(const float4*)(als + (size_t)s * 4);
        float e = ((hq == 0) ? s4.x : (hq == 1) ? s4.y : (hq == 2) ? s4.z : s4.w) + adq;
        e = e > 0.f ? e : 0.2f * e;
        float w = __expf(e);
        denl += w;
        float w0 = __shfl_sync(0xffffffffu, w, 0, 4);
        float w1 = __shfl_sync(0xffffffffu, w, 1, 4);
        float w2 = __shfl_sync(0xffffffffu, w, 2, 4);
        float w3 = __shfl_sync(0xffffffffu, w, 3, 4);
        float2 v = *(const float2*)(out1 + (size_t)s * 64 + lane * 2);
        acc0.x = fmaf(w0, v.x, acc0.x); acc0.y = fmaf(w0, v.y, acc0.y);
        acc1.x = fmaf(w1, v.x, acc1.x); acc1.y = fmaf(w1, v.y, acc1.y);
        acc2.x = fmaf(w2, v.x, acc2.x); acc2.y = fmaf(w2, v.y, acc2.y);
        acc3.x = fmaf(w3, v.x, acc3.x); acc3.y = fmaf(w3, v.y, acc3.y);
    }
    float d0 = __shfl_sync(0xffffffffu, denl, 0, 4);
    float d1 = __shfl_sync(0xffffffffu, denl, 1, 4);
    float d2 = __shfl_sync(0xffffffffu, denl, 2, 4);
    float d3 = __shfl_sync(0xffffffffu, denl, 3, 4);
    float i0 = 1.f / d0, i1 = 1.f / d1, i2 = 1.f / d2, i3 = 1.f / d3;

    float* zp = Z + (size_t)node * 256 + lane * 2;
    *(float2*)(zp +   0) = make_float2(acc0.x * i0, acc0.y * i0);
    *(float2*)(zp +  64) = make_float2(acc1.x * i1, acc1.y * i1);
    *(float2*)(zp + 128) = make_float2(acc2.x * i2, acc2.y * i2);
    *(float2*)(zp + 192) = make_float2(acc3.x * i3, acc3.y * i3);
}

// ---------------- epilogue GEMM [n,256]@[256,32] + bias/elu/logsoftmax ----
__global__ __launch_bounds__(256)
void ep_gemm_kernel(const float* __restrict__ Z, const float* __restrict__ wcat,
                    const float* __restrict__ b2, float* __restrict__ y, int n)
{
    __shared__ float Ws[256][32];       // 32 KB
    __shared__ float Zs[16][129];       // transposed k-chunk, 8.2 KB

    const int tid = threadIdx.x;
    const int tx = tid & 7;             // col group (4 cols)
    const int ty = tid >> 3;            // row group (4 rows), 0..31
    const int row0 = blockIdx.x * 128;

    for (int t = tid; t < 2048; t += 256)
        *(float4*)&Ws[t >> 3][(t & 7) * 4] = *(const float4*)(wcat + t * 4);

    float acc[4][4];
#pragma unroll
    for (int i = 0; i < 4; i++)
#pragma unroll
        for (int j = 0; j < 4; j++) acc[i][j] = 0.f;

    for (int ck = 0; ck < 16; ck++) {
        __syncthreads();
        // load 128 rows x 16 k, transposed into Zs[k][r]
#pragma unroll
        for (int t = 0; t < 2; t++) {
            int q = tid + t * 256;      // 0..511
            int r = q >> 2, kc4 = q & 3;
            int gr = row0 + r;
            float4 v = (gr < n)
                ? *(const float4*)(Z + (size_t)gr * 256 + ck * 16 + kc4 * 4)
                : make_float4(0.f, 0.f, 0.f, 0.f);
            Zs[kc4 * 4 + 0][r] = v.x;
            Zs[kc4 * 4 + 1][r] = v.y;
            Zs[kc4 * 4 + 2][r] = v.z;
            Zs[kc4 * 4 + 3][r] = v.w;
        }
        __syncthreads();
#pragma unroll
        for (int k = 0; k < 16; k++) {
            float4 b = *(float4*)&Ws[ck * 16 + k][tx * 4];
            float a0 = Zs[k][ty * 4 + 0];
            float a1 = Zs[k][ty * 4 + 1];
            float a2 = Zs[k][ty * 4 + 2];
            float a3 = Zs[k][ty * 4 + 3];
            acc[0][0] = fmaf(a0, b.x, acc[0][0]); acc[0][1] = fmaf(a0, b.y, acc[0][1]);
            acc[0][2] = fmaf(a0, b.z, acc[0][2]); acc[0][3] = fmaf(a0, b.w, acc[0][3]);
            acc[1][0] = fmaf(a1, b.x, acc[1][0]); acc[1][1] = fmaf(a1, b.y, acc[1][1]);
            acc[1][2] = fmaf(a1, b.z, acc[1][2]); acc[1][3] = fmaf(a1, b.w, acc[1][3]);
            acc[2][0] = fmaf(a2, b.x, acc[2][0]); acc[2][1] = fmaf(a2, b.y, acc[2][1]);
            acc[2][2] = fmaf(a2, b.z, acc[2][2]); acc[2][3] = fmaf(a2, b.w, acc[2][3]);
            acc[3][0] = fmaf(a3, b.x, acc[3][0]); acc[3][1] = fmaf(a3, b.y, acc[3][1]);
            acc[3][2] = fmaf(a3, b.z, acc[3][2]); acc[3][3] = fmaf(a3, b.w, acc[3][3]);
        }
    }

    // epilogue: + b2, elu, log_softmax over the 32 cols (8 tx lanes x 4)
    float4 bb = *(const float4*)(b2 + tx * 4);
#pragma unroll
    for (int i = 0; i < 4; i++) {
        acc[i][0] += bb.x; acc[i][1] += bb.y; acc[i][2] += bb.z; acc[i][3] += bb.w;
#pragma unroll
        for (int j = 0; j < 4; j++)
            acc[i][j] = acc[i][j] > 0.f ? acc[i][j] : expm1f(acc[i][j]);
        float m = fmaxf(fmaxf(acc[i][0], acc[i][1]), fmaxf(acc[i][2], acc[i][3]));
#pragma unroll
        for (int off = 1; off < 8; off <<= 1)
            m = fmaxf(m, __shfl_xor_sync(0xffffffffu, m, off));
        float s = expf(acc[i][0] - m) + expf(acc[i][1] - m)
                + expf(acc[i][2] - m) + expf(acc[i][3] - m);
#pragma unroll
        for (int off = 1; off < 8; off <<= 1)
            s += __shfl_xor_sync(0xffffffffu, s, off);
        float ls = m + logf(s);
        int gr = row0 + ty * 4 + i;
        if (gr < n)
            *(float4*)(y + (size_t)gr * 32 + tx * 4) =
                make_float4(acc[i][0] - ls, acc[i][1] - ls,
                            acc[i][2] - ls, acc[i][3] - ls);
    }
}

// ---------------------------------------------------------------------------
extern "C" void kernel_launch(void* const* d_in, const int* in_sizes, int n_in,
                              void* d_out, int out_size)
{
    const float* x   = (const float*)d_in[0];
    const int*   ei  = (const int*)d_in[1];
    const float* W1  = (const float*)d_in[2];
    const float* as1 = (const float*)d_in[3];
    const float* ad1 = (const float*)d_in[4];
    const float* b1  = (const float*)d_in[5];
    const float* W2  = (const float*)d_in[6];
    const float* as2 = (const float*)d_in[7];
    const float* ad2 = (const float*)d_in[8];
    const float* b2  = (const float*)d_in[9];
    float*       y   = (float*)d_out;

    const int n = in_sizes[0] / 128;
    const int E = in_sizes[1] / 2;
    const int* se = ei;
    const int* de = ei + E;

    float *h1, *als1, *ald1, *out1, *als2, *ald2, *Zb, *wsd, *wcat;
    int *rowptr, *cursor, *bsum, *ssrc;
    cudaGetSymbolAddress((void**)&h1,     g_h1);
    cudaGetSymbolAddress((void**)&als1,   g_als1);
    cudaGetSymbolAddress((void**)&ald1,   g_ald1);
    cudaGetSymbolAddress((void**)&out1,   g_out1);
    cudaGetSymbolAddress((void**)&als2,   g_als2);
    cudaGetSymbolAddress((void**)&ald2,   g_ald2);
    cudaGetSymbolAddress((void**)&Zb,     g_Z);
    cudaGetSymbolAddress((void**)&wsd,    g_wsd);
    cudaGetSymbolAddress((void**)&wcat,   g_wcat);
    cudaGetSymbolAddress((void**)&rowptr, g_rowptr);
    cudaGetSymbolAddress((void**)&cursor, g_cursor);
    cudaGetSymbolAddress((void**)&bsum,   g_bsum);
    cudaGetSymbolAddress((void**)&ssrc,   g_ssrc);

    static cudaStream_t s2 = nullptr;
    static cudaEvent_t evFork = nullptr, evJoin = nullptr;
    if (!s2) {
        cudaStreamCreateWithFlags(&s2, cudaStreamNonBlocking);
        cudaEventCreateWithFlags(&evFork, cudaEventDisableTiming);
        cudaEventCreateWithFlags(&evJoin, cudaEventDisableTiming);
    }

    const int nb = (n + 2047) / 2048;

    // ---- fork: weight folds + CSR build on s2, concurrent with GEMM1/al1 --
    cudaEventRecord(evFork, 0);
    cudaStreamWaitEvent(s2, evFork, 0);
    build_wsd<<<1, 512, 0, s2>>>(W2, as2, ad2, wsd);
    build_wcat<<<32, 256, 0, s2>>>(W2, wcat);
    cudaMemsetAsync(rowptr, 0, (size_t)n * sizeof(int), s2);
    hist_kernel<<<(E + 255) / 256, 256, 0, s2>>>(de, E, rowptr);
    scan_k1<<<nb, 256, 0, s2>>>(rowptr, n, bsum);
    scan_k2<<<1, 32, 0, s2>>>(bsum, nb);
    scan_k3<<<(n + 255) / 256, 256, 0, s2>>>(rowptr, n, bsum, cursor, E);
    scatter_kernel<<<(E + 255) / 256, 256, 0, s2>>>(se, de, E, cursor, ssrc);
    cudaEventRecord(evJoin, s2);

    // ---- layer 1 dense part (main stream, overlapped with CSR) ----
    gemm_kernel<128, 64><<<(n + 127) / 128, 128>>>(x, W1, h1, n);
    al_kernel<16><<<(n * 4 + 255) / 256, 256>>>(h1, as1, ad1, als1, ald1, n);

    // ---- join, then layer-1 aggregation (adds b1) ----
    cudaStreamWaitEvent(0, evJoin, 0);
    agg_csr_kernel<16><<<(int)(((long long)n * 16 + 255) / 256), 256>>>(
        rowptr, ssrc, als1, ald1, h1, b1, out1, n);

    // ---- layer 2: logits from out1, dual-space aggregation, epilogue GEMM -
    als2_kernel<<<(int)(((long long)n * 32 + 255) / 256), 256>>>(
        out1, wsd, als2, ald2, n);
    agg2_dual_kernel<<<(int)(((long long)n * 32 + 255) / 256), 256>>>(
        rowptr, ssrc, als2, ald2, out1, Zb, n);
    ep_gemm_kernel<<<(n + 127) / 128, 256>>>(Zb, wcat, b2, y, n);
}